// round 3
// baseline (speedup 1.0000x reference)
#include <cuda_runtime.h>
#include <cuda_fp16.h>
#include <stdint.h>

#define TOKENS 8192
#define DIN    4096
#define DOUT   4096
#define RANK   256

// ---------------- scratch (static device globals: allocation-free) ----------------
__device__ __half g_xh[(size_t)TOKENS * DIN];   // x in fp16
__device__ __half g_qh[(size_t)DOUT * DIN];     // dequantized Q
__device__ __half g_rh[(size_t)RANK * DIN];     // dequantized R
__device__ __half g_lh[(size_t)DOUT * RANK];    // dequantized L
__device__ __half g_xr[(size_t)TOKENS * RANK];  // xr = x @ R^T in fp16

// ---------------- small conversion kernels ----------------
__global__ void cvt_x_kernel(const float* __restrict__ x) {
    int i = blockIdx.x * blockDim.x + threadIdx.x;  // grid sized exactly
    float4 v = reinterpret_cast<const float4*>(x)[i];
    __half2* o = reinterpret_cast<__half2*>(g_xh);
    o[2 * i]     = __floats2half2_rn(v.x, v.y);
    o[2 * i + 1] = __floats2half2_rn(v.z, v.w);
}

// groupwise dequant: out[r][c] = values[r][c] * scales[r][c/128], fp16 result
__global__ void deq_kernel(const int* __restrict__ v, const float* __restrict__ s,
                           __half* __restrict__ o, int cols_log2) {
    int i = blockIdx.x * blockDim.x + threadIdx.x;  // grid sized exactly
    int4 q = reinterpret_cast<const int4*>(v)[i];
    int e = i << 2;
    int r = e >> cols_log2;
    int c = e & ((1 << cols_log2) - 1);
    float sc = s[(r << (cols_log2 - 7)) + (c >> 7)];
    __half2* po = reinterpret_cast<__half2*>(o);
    po[2 * i]     = __floats2half2_rn(q.x * sc, q.y * sc);
    po[2 * i + 1] = __floats2half2_rn(q.z * sc, q.w * sc);
}

// ---------------- GEMM building blocks (mma.sync m16n8k16 f16->f32) ----------------
__device__ __forceinline__ void cp_async16(uint32_t dst, const void* src) {
    asm volatile("cp.async.cg.shared.global [%0], [%1], 16;\n" :: "r"(dst), "l"(src));
}
__device__ __forceinline__ void cp_commit() {
    asm volatile("cp.async.commit_group;\n" ::: "memory");
}
template <int N>
__device__ __forceinline__ void cp_wait() {
    asm volatile("cp.async.wait_group %0;\n" :: "n"(N) : "memory");
}
__device__ __forceinline__ void ldsm4(uint32_t r[4], uint32_t addr) {
    asm volatile("ldmatrix.sync.aligned.m8n8.x4.shared.b16 {%0,%1,%2,%3}, [%4];\n"
                 : "=r"(r[0]), "=r"(r[1]), "=r"(r[2]), "=r"(r[3]) : "r"(addr));
}
__device__ __forceinline__ void mma16816(float c[4], const uint32_t a[4],
                                         uint32_t b0, uint32_t b1) {
    asm volatile("mma.sync.aligned.m16n8k16.row.col.f32.f16.f16.f32 "
                 "{%0,%1,%2,%3},{%4,%5,%6,%7},{%8,%9},{%0,%1,%2,%3};\n"
                 : "+f"(c[0]), "+f"(c[1]), "+f"(c[2]), "+f"(c[3])
                 : "r"(a[0]), "r"(a[1]), "r"(a[2]), "r"(a[3]), "r"(b0), "r"(b1));
}

// Smem tile layout (K-major, BK=64 halves = 128B rows):
// addr(row, col) = base + row*128 + (((col>>3) ^ (row&7)) << 4) + (col&7)*2
// 8-chunk XOR swizzle -> conflict-free ldmatrix and cp.async stores.
template <int ROWS>
__device__ __forceinline__ void load_tile(uint32_t sbase, const __half* __restrict__ g,
                                          int ld, int row0, int k0, int tid) {
    #pragma unroll
    for (int j = 0; j < ROWS / 32; j++) {        // ROWS*8 chunks of 16B, 256 threads
        int idx = tid + j * 256;
        int r = idx >> 3;
        int ch = idx & 7;
        const __half* src = g + (size_t)(row0 + r) * ld + (k0 + ch * 8);
        uint32_t dst = sbase + r * 128 + ((ch ^ (r & 7)) << 4);
        cp_async16(dst, src);
    }
}

// ------------------------------------------------------------------------------
// HMMA GEMM: CTA tile 128 x BN, BK=64, 8 warps as 2(M) x 4(N), warp tile 64x(BN/4).
// Fused second K-loop: iterations >= MAIN_ITERS pull from (A2, B2).
// 4-stage cp.async pipeline, ONE __syncthreads per K-iteration.
// ------------------------------------------------------------------------------
template <int BN, int TOTAL_ITERS, int MAIN_ITERS, bool FP16_OUT>
__global__ void __launch_bounds__(256, 1) hmma_gemm_kernel(
    const __half* __restrict__ A1, int lda1, const __half* __restrict__ B1, int ldb1,
    const __half* __restrict__ A2, int lda2, const __half* __restrict__ B2, int ldb2,
    const float* __restrict__ bias,
    float* __restrict__ outf, __half* __restrict__ outh, int out_ld)
{
    constexpr int A_BYTES = 128 * 128;
    constexpr int B_BYTES = BN * 128;
    constexpr int STG     = A_BYTES + B_BYTES;
    constexpr int WNT     = BN / 32;   // n8 mma tiles per warp (warp n-width = BN/4)

    extern __shared__ char smem[];
    uint32_t s;
    asm("{ .reg .u64 t; cvta.to.shared.u64 t, %1; cvt.u32.u64 %0, t; }" : "=r"(s) : "l"(smem));

    const int tid  = threadIdx.x;
    const int lane = tid & 31;
    const int wid  = tid >> 5;
    const int wm   = wid >> 2;
    const int wn   = wid & 3;
    const int m0   = blockIdx.x * 128;
    const int n0   = blockIdx.y * BN;

    float c[4][WNT][4];
    #pragma unroll
    for (int i = 0; i < 4; i++)
        #pragma unroll
        for (int j = 0; j < WNT; j++)
            #pragma unroll
            for (int k = 0; k < 4; k++) c[i][j][k] = 0.f;

    auto issue = [&](int kt, int st) {
        uint32_t da = s + st * STG;
        uint32_t db = da + A_BYTES;
        if (kt < MAIN_ITERS) {
            load_tile<128>(da, A1, lda1, m0, kt * 64, tid);
            load_tile<BN> (db, B1, ldb1, n0, kt * 64, tid);
        } else {
            int k2 = (kt - MAIN_ITERS) * 64;
            load_tile<128>(da, A2, lda2, m0, k2, tid);
            load_tile<BN> (db, B2, ldb2, n0, k2, tid);
        }
    };

    // prologue: stages 0..2
    issue(0, 0); cp_commit();
    issue(1, 1); cp_commit();
    issue(2, 2); cp_commit();

    const int lr = lane & 15;
    const int lc = lane >> 4;

    for (int kt = 0; kt < TOTAL_ITERS; kt++) {
        cp_wait<2>();
        __syncthreads();   // stage kt visible to all; compute(kt-1) done before reuse

        // refill the stage freed by compute(kt-1)
        if (kt + 3 < TOTAL_ITERS) issue(kt + 3, (kt + 3) & 3);
        cp_commit();       // empty group near the tail keeps wait<2> arithmetic uniform

        const int st = kt & 3;
        const uint32_t sA = s + st * STG;
        const uint32_t sB = sA + A_BYTES;

        #pragma unroll
        for (int ks = 0; ks < 4; ks++) {
            uint32_t a[4][4];
            uint32_t b[WNT / 2][4];
            #pragma unroll
            for (int im = 0; im < 4; im++) {
                int row = wm * 64 + im * 16 + lr;
                int ch = (ks * 2 + lc) ^ (row & 7);
                ldsm4(a[im], sA + row * 128 + (ch << 4));
            }
            #pragma unroll
            for (int j = 0; j < WNT / 2; j++) {
                int row = wn * (BN / 4) + j * 16 + lr;
                int ch = (ks * 2 + lc) ^ (row & 7);
                ldsm4(b[j], sB + row * 128 + (ch << 4));
            }
            #pragma unroll
            for (int im = 0; im < 4; im++) {
                #pragma unroll
                for (int jn = 0; jn < WNT; jn++) {
                    mma16816(c[im][jn], a[im], b[jn >> 1][jn & 1], b[jn >> 1][2 + (jn & 1)]);
                }
            }
        }
    }

    // ---- epilogue ----
    #pragma unroll
    for (int im = 0; im < 4; im++) {
        #pragma unroll
        for (int jn = 0; jn < WNT; jn++) {
            int row = m0 + wm * 64 + im * 16 + (lane >> 2);
            int col = n0 + wn * (BN / 4) + jn * 8 + (lane & 3) * 2;
            if constexpr (FP16_OUT) {
                __half2 v0 = __floats2half2_rn(c[im][jn][0], c[im][jn][1]);
                __half2 v1 = __floats2half2_rn(c[im][jn][2], c[im][jn][3]);
                *reinterpret_cast<__half2*>(&outh[(size_t)row * out_ld + col]) = v0;
                *reinterpret_cast<__half2*>(&outh[(size_t)(row + 8) * out_ld + col]) = v1;
            } else {
                float b0 = bias[col];
                float b1 = bias[col + 1];
                float2 v0 = make_float2(c[im][jn][0] + b0, c[im][jn][1] + b1);
                float2 v1 = make_float2(c[im][jn][2] + b0, c[im][jn][3] + b1);
                *reinterpret_cast<float2*>(outf + (size_t)row * out_ld + col) = v0;
                *reinterpret_cast<float2*>(outf + (size_t)(row + 8) * out_ld + col) = v1;
            }
        }
    }
}

// ---------------- launch ----------------
extern "C" void kernel_launch(void* const* d_in, const int* in_sizes, int n_in,
                              void* d_out, int out_size) {
    const float* x    = (const float*)d_in[0];
    const int*   qv   = (const int*)  d_in[1];
    const float* qs   = (const float*)d_in[2];
    const int*   lv   = (const int*)  d_in[3];
    const float* ls   = (const float*)d_in[4];
    const int*   rv   = (const int*)  d_in[5];
    const float* rs   = (const float*)d_in[6];
    const float* bias = (const float*)d_in[7];
    float* out = (float*)d_out;

    __half *pxh, *pq, *pr, *pl, *pxr;
    cudaGetSymbolAddress((void**)&pxh, g_xh);
    cudaGetSymbolAddress((void**)&pq,  g_qh);
    cudaGetSymbolAddress((void**)&pr,  g_rh);
    cudaGetSymbolAddress((void**)&pl,  g_lh);
    cudaGetSymbolAddress((void**)&pxr, g_xr);

    // xr kernel: BN=128, K=4096 (no fused loop), fp16 out
    auto kxr = hmma_gemm_kernel<128, DIN / 64, DIN / 64, true>;
    // main kernel: BN=256, K=4096 + fused K=256 low-rank, fp32 out + bias
    auto kmain = hmma_gemm_kernel<256, DIN / 64 + RANK / 64, DIN / 64, false>;

    const int SMEM_XR   = 4 * (128 + 128) * 128;  // 128 KB
    const int SMEM_MAIN = 4 * (128 + 256) * 128;  // 192 KB
    cudaFuncSetAttribute(kxr,   cudaFuncAttributeMaxDynamicSharedMemorySize, SMEM_XR);
    cudaFuncSetAttribute(kmain, cudaFuncAttributeMaxDynamicSharedMemorySize, SMEM_MAIN);

    // pre-pass: fp16 conversion + groupwise dequant
    cvt_x_kernel<<<(TOKENS * DIN / 4) / 256, 256>>>(x);
    deq_kernel<<<((size_t)DOUT * DIN / 4) / 256, 256>>>(qv, qs, pq, 12);
    deq_kernel<<<((size_t)RANK * DIN / 4) / 256, 256>>>(rv, rs, pr, 12);
    deq_kernel<<<((size_t)DOUT * RANK / 4) / 256, 256>>>(lv, ls, pl, 8);

    // xr = x @ R^T  (fp16 out)
    kxr<<<dim3(TOKENS / 128, RANK / 128), 256, SMEM_XR>>>(
        pxh, DIN, pr, DIN, pxh, DIN, pr, DIN, nullptr, nullptr, pxr, RANK);

    // out = x @ Q^T + xr @ L^T + bias  (fused second K-loop)
    kmain<<<dim3(TOKENS / 128, DOUT / 256), 256, SMEM_MAIN>>>(
        pxh, DIN, pq, DIN, pxr, RANK, pl, RANK, bias, out, nullptr, DOUT);
}

// round 4
// speedup vs baseline: 1.1358x; 1.1358x over previous
#include <cuda_runtime.h>
#include <cuda_fp16.h>
#include <cuda.h>
#include <stdint.h>

#define TOKENS 8192
#define DIN    4096
#define DOUT   4096
#define RANK   256

#define STAGES    3
#define STG_BYTES (256 * 128)              // (128 A rows + 128 B rows) x 128B
#define SMEM_SIZE (2048 + STAGES * STG_BYTES)   // 100352 B -> 2 CTAs/SM

// ---------------- scratch (static device globals: allocation-free) ----------------
__device__ __half g_xh[(size_t)TOKENS * DIN];   // x in fp16
__device__ __half g_qh[(size_t)DOUT * DIN];     // dequantized Q
__device__ __half g_rh[(size_t)RANK * DIN];     // dequantized R
__device__ __half g_lh[(size_t)DOUT * RANK];    // dequantized L
__device__ __half g_xr[(size_t)TOKENS * RANK];  // xr = x @ R^T in fp16

// ---------------- small conversion kernels ----------------
__global__ void cvt_x_kernel(const float* __restrict__ x) {
    int i = blockIdx.x * blockDim.x + threadIdx.x;
    float4 v = reinterpret_cast<const float4*>(x)[i];
    __half2* o = reinterpret_cast<__half2*>(g_xh);
    o[2 * i]     = __floats2half2_rn(v.x, v.y);
    o[2 * i + 1] = __floats2half2_rn(v.z, v.w);
}

__global__ void deq_kernel(const int* __restrict__ v, const float* __restrict__ s,
                           __half* __restrict__ o, int cols_log2) {
    int i = blockIdx.x * blockDim.x + threadIdx.x;
    int4 q = reinterpret_cast<const int4*>(v)[i];
    int e = i << 2;
    int r = e >> cols_log2;
    int c = e & ((1 << cols_log2) - 1);
    float sc = s[(r << (cols_log2 - 7)) + (c >> 7)];
    __half2* po = reinterpret_cast<__half2*>(o);
    po[2 * i]     = __floats2half2_rn(q.x * sc, q.y * sc);
    po[2 * i + 1] = __floats2half2_rn(q.z * sc, q.w * sc);
}

// ---------------- PTX helpers ----------------
__device__ __forceinline__ uint32_t smem_u32(const void* p) {
    uint32_t a;
    asm("{ .reg .u64 t; cvta.to.shared.u64 t, %1; cvt.u32.u64 %0, t; }" : "=r"(a) : "l"(p));
    return a;
}
#define MBARRIER_INIT(addr, cnt) \
    asm volatile("mbarrier.init.shared.b64 [%0], %1;" :: "r"(addr), "r"(cnt) : "memory")
#define MBARRIER_EXPECT_TX(addr, bytes) \
    asm volatile("mbarrier.arrive.expect_tx.shared.b64 _, [%0], %1;" \
                 :: "r"(addr), "r"(bytes) : "memory")
__device__ __forceinline__ void mbar_wait_parity(uint32_t mbar, uint32_t parity) {
    uint32_t done;
    asm volatile("{ .reg .pred p; mbarrier.try_wait.parity.acquire.cta.shared::cta.b64 p, [%1], %2;"
                 " selp.b32 %0, 1, 0, p; }" : "=r"(done) : "r"(mbar), "r"(parity) : "memory");
    if (!done) {
        asm volatile("{ .reg .pred P1; WL_%=:"
                     " mbarrier.try_wait.parity.acquire.cta.shared::cta.b64 P1, [%0], %1, 0x989680;"
                     " @P1 bra.uni WD_%=; bra.uni WL_%=; WD_%=: }"
                     :: "r"(mbar), "r"(parity) : "memory");
    }
}
#define TMA_LOAD_2D(dst, map, cx, cy, mbar) \
    asm volatile("cp.async.bulk.tensor.2d.shared::cta.global.tile.mbarrier::complete_tx::bytes " \
                 "[%0], [%1, {%2, %3}], [%4];" \
                 :: "r"(dst), "l"(map), "r"(cx), "r"(cy), "r"(mbar) : "memory")
#define FENCE_PROXY_ASYNC() asm volatile("fence.proxy.async.shared::cta;" ::: "memory")

__device__ __forceinline__ void ldsm4(uint32_t r[4], uint32_t addr) {
    asm volatile("ldmatrix.sync.aligned.m8n8.x4.shared.b16 {%0,%1,%2,%3}, [%4];\n"
                 : "=r"(r[0]), "=r"(r[1]), "=r"(r[2]), "=r"(r[3]) : "r"(addr));
}
__device__ __forceinline__ void mma16816(float c[4], const uint32_t a[4],
                                         uint32_t b0, uint32_t b1) {
    asm volatile("mma.sync.aligned.m16n8k16.row.col.f32.f16.f16.f32 "
                 "{%0,%1,%2,%3},{%4,%5,%6,%7},{%8,%9},{%0,%1,%2,%3};\n"
                 : "+f"(c[0]), "+f"(c[1]), "+f"(c[2]), "+f"(c[3])
                 : "r"(a[0]), "r"(a[1]), "r"(a[2]), "r"(a[3]), "r"(b0), "r"(b1));
}

// ------------------------------------------------------------------------------
// TMA-fed HMMA GEMM. CTA tile 128x128, BK=64, 8 warps as 2(M) x 4(N), warp 64x32.
// TMA SW128 layout == addr(row,col) = row*128 + (((col>>3) ^ (row&7))<<4) + (col&7)*2
// 3-stage mbarrier pipeline, single producer thread, ONE __syncthreads per iter.
// Iterations >= MAIN_ITERS pull from (tmA2, tmB2) -- fused low-rank K-loop.
// ------------------------------------------------------------------------------
template <int TOTAL_ITERS, int MAIN_ITERS, bool FP16_OUT>
__global__ void __launch_bounds__(256, 2) tma_gemm_kernel(
    const __grid_constant__ CUtensorMap tmA1,
    const __grid_constant__ CUtensorMap tmB1,
    const __grid_constant__ CUtensorMap tmA2,
    const __grid_constant__ CUtensorMap tmB2,
    const float* __restrict__ bias,
    float* __restrict__ outf, __half* __restrict__ outh, int out_ld)
{
    extern __shared__ char smem[];
    const uint32_t sb    = smem_u32(smem);
    const uint32_t fullb = sb;                              // STAGES x 8B mbarriers
    const uint32_t tiles = (sb + 64 + 1023) & ~1023u;       // 1024-aligned for SW128

    const int tid  = threadIdx.x;
    const int lane = tid & 31;
    const int wid  = tid >> 5;
    const int wm   = wid >> 2;
    const int wn   = wid & 3;
    const int m0   = blockIdx.x * 128;
    const int n0   = blockIdx.y * 128;

    if (tid == 0) {
        #pragma unroll
        for (int s = 0; s < STAGES; s++) MBARRIER_INIT(fullb + 8 * s, 1);
        FENCE_PROXY_ASYNC();
    }
    __syncthreads();

    auto issue = [&](int kt, int st) {
        uint32_t da = tiles + st * STG_BYTES;
        uint32_t db = da + 128 * 128;
        MBARRIER_EXPECT_TX(fullb + 8 * st, STG_BYTES);
        if (kt < MAIN_ITERS) {
            TMA_LOAD_2D(da, &tmA1, kt * 64, m0, fullb + 8 * st);
            TMA_LOAD_2D(db, &tmB1, kt * 64, n0, fullb + 8 * st);
        } else {
            int k2 = (kt - MAIN_ITERS) * 64;
            TMA_LOAD_2D(da, &tmA2, k2, m0, fullb + 8 * st);
            TMA_LOAD_2D(db, &tmB2, k2, n0, fullb + 8 * st);
        }
    };

    if (tid == 0) {
        #pragma unroll
        for (int p = 0; p < STAGES; p++)
            if (p < TOTAL_ITERS) issue(p, p);
    }

    float c[4][4][4];
    #pragma unroll
    for (int i = 0; i < 4; i++)
        #pragma unroll
        for (int j = 0; j < 4; j++)
            #pragma unroll
            for (int k = 0; k < 4; k++) c[i][j][k] = 0.f;

    const int lr = lane & 15;
    const int lc = lane >> 4;

    int st = 0, ph = 0;
    for (int kt = 0; kt < TOTAL_ITERS; kt++) {
        mbar_wait_parity(fullb + 8 * st, ph);

        const uint32_t sA = tiles + st * STG_BYTES;
        const uint32_t sB = sA + 128 * 128;

        #pragma unroll
        for (int ks = 0; ks < 4; ks++) {
            uint32_t a[4][4];
            uint32_t b[2][4];
            #pragma unroll
            for (int im = 0; im < 4; im++) {
                int row = wm * 64 + im * 16 + lr;
                int ch = (ks * 2 + lc) ^ (row & 7);
                ldsm4(a[im], sA + row * 128 + (ch << 4));
            }
            #pragma unroll
            for (int j = 0; j < 2; j++) {
                int row = wn * 32 + j * 16 + lr;
                int ch = (ks * 2 + lc) ^ (row & 7);
                ldsm4(b[j], sB + row * 128 + (ch << 4));
            }
            #pragma unroll
            for (int im = 0; im < 4; im++) {
                #pragma unroll
                for (int jn = 0; jn < 4; jn++) {
                    mma16816(c[im][jn], a[im], b[jn >> 1][jn & 1], b[jn >> 1][2 + (jn & 1)]);
                }
            }
        }

        __syncthreads();                       // all warps done reading stage st
        if (tid == 0 && kt + STAGES < TOTAL_ITERS) issue(kt + STAGES, st);

        if (++st == STAGES) { st = 0; ph ^= 1; }
    }

    // ---- epilogue ----
    #pragma unroll
    for (int im = 0; im < 4; im++) {
        #pragma unroll
        for (int jn = 0; jn < 4; jn++) {
            int row = m0 + wm * 64 + im * 16 + (lane >> 2);
            int col = n0 + wn * 32 + jn * 8 + (lane & 3) * 2;
            if constexpr (FP16_OUT) {
                __half2 v0 = __floats2half2_rn(c[im][jn][0], c[im][jn][1]);
                __half2 v1 = __floats2half2_rn(c[im][jn][2], c[im][jn][3]);
                *reinterpret_cast<__half2*>(&outh[(size_t)row * out_ld + col]) = v0;
                *reinterpret_cast<__half2*>(&outh[(size_t)(row + 8) * out_ld + col]) = v1;
            } else {
                float b0 = bias[col];
                float b1 = bias[col + 1];
                float2 v0 = make_float2(c[im][jn][0] + b0, c[im][jn][1] + b1);
                float2 v1 = make_float2(c[im][jn][2] + b0, c[im][jn][3] + b1);
                *reinterpret_cast<float2*>(outf + (size_t)row * out_ld + col) = v0;
                *reinterpret_cast<float2*>(outf + (size_t)(row + 8) * out_ld + col) = v1;
            }
        }
    }
}

// ---------------- host: tensor maps + launch ----------------
typedef CUresult (*EncodeTiledFn)(
    CUtensorMap*, CUtensorMapDataType, cuuint32_t, void*,
    const cuuint64_t*, const cuuint64_t*, const cuuint32_t*, const cuuint32_t*,
    CUtensorMapInterleave, CUtensorMapSwizzle, CUtensorMapL2promotion,
    CUtensorMapFloatOOBfill);

static void make_map_f16(EncodeTiledFn enc, CUtensorMap* tm, void* base,
                         uint64_t dim0, uint64_t dim1, uint64_t pitch_bytes) {
    uint64_t dims[2] = {dim0, dim1};
    uint64_t strides[1] = {pitch_bytes};
    uint32_t box[2] = {64, 128};
    uint32_t es[2] = {1, 1};
    enc(tm, CU_TENSOR_MAP_DATA_TYPE_FLOAT16, 2, base, dims, strides, box, es,
        CU_TENSOR_MAP_INTERLEAVE_NONE, CU_TENSOR_MAP_SWIZZLE_128B,
        CU_TENSOR_MAP_L2_PROMOTION_L2_128B, CU_TENSOR_MAP_FLOAT_OOB_FILL_NONE);
}

extern "C" void kernel_launch(void* const* d_in, const int* in_sizes, int n_in,
                              void* d_out, int out_size) {
    const float* x    = (const float*)d_in[0];
    const int*   qv   = (const int*)  d_in[1];
    const float* qs   = (const float*)d_in[2];
    const int*   lv   = (const int*)  d_in[3];
    const float* ls   = (const float*)d_in[4];
    const int*   rv   = (const int*)  d_in[5];
    const float* rs   = (const float*)d_in[6];
    const float* bias = (const float*)d_in[7];
    float* out = (float*)d_out;

    __half *pxh, *pq, *pr, *pl, *pxr;
    cudaGetSymbolAddress((void**)&pxh, g_xh);
    cudaGetSymbolAddress((void**)&pq,  g_qh);
    cudaGetSymbolAddress((void**)&pr,  g_rh);
    cudaGetSymbolAddress((void**)&pl,  g_lh);
    cudaGetSymbolAddress((void**)&pxr, g_xr);

    EncodeTiledFn enc = nullptr;
    {
        void* fp = nullptr;
        cudaDriverEntryPointQueryResult st;
        cudaGetDriverEntryPointByVersion("cuTensorMapEncodeTiled", &fp, 12000,
                                         cudaEnableDefault, &st);
        enc = (EncodeTiledFn)fp;
    }

    CUtensorMap tmX, tmQ, tmR, tmXR, tmL;
    make_map_f16(enc, &tmX,  pxh, DIN,  TOKENS, (uint64_t)DIN * 2);
    make_map_f16(enc, &tmQ,  pq,  DIN,  DOUT,   (uint64_t)DIN * 2);
    make_map_f16(enc, &tmR,  pr,  DIN,  RANK,   (uint64_t)DIN * 2);
    make_map_f16(enc, &tmXR, pxr, RANK, TOKENS, (uint64_t)RANK * 2);
    make_map_f16(enc, &tmL,  pl,  RANK, DOUT,   (uint64_t)RANK * 2);

    auto kxr   = tma_gemm_kernel<DIN / 64, DIN / 64, true>;
    auto kmain = tma_gemm_kernel<DIN / 64 + RANK / 64, DIN / 64, false>;
    cudaFuncSetAttribute(kxr,   cudaFuncAttributeMaxDynamicSharedMemorySize, SMEM_SIZE);
    cudaFuncSetAttribute(kmain, cudaFuncAttributeMaxDynamicSharedMemorySize, SMEM_SIZE);

    // pre-pass: fp16 conversion + groupwise dequant
    cvt_x_kernel<<<(TOKENS * DIN / 4) / 256, 256>>>(x);
    deq_kernel<<<((size_t)DOUT * DIN / 4) / 256, 256>>>(qv, qs, pq, 12);
    deq_kernel<<<((size_t)RANK * DIN / 4) / 256, 256>>>(rv, rs, pr, 12);
    deq_kernel<<<((size_t)DOUT * RANK / 4) / 256, 256>>>(lv, ls, pl, 8);

    // xr = x @ R^T  (fp16 out)
    kxr<<<dim3(TOKENS / 128, RANK / 128), 256, SMEM_SIZE>>>(
        tmX, tmR, tmX, tmR, nullptr, nullptr, pxr, RANK);

    // out = x @ Q^T + xr @ L^T + bias  (fused second K-loop)
    kmain<<<dim3(TOKENS / 128, DOUT / 128), 256, SMEM_SIZE>>>(
        tmX, tmQ, tmXR, tmL, bias, out, nullptr, DOUT);
}

// round 5
// speedup vs baseline: 1.2190x; 1.0733x over previous
#include <cuda_runtime.h>
#include <cuda_fp16.h>
#include <cuda.h>
#include <stdint.h>

#define TOKENS 8192
#define DIN    4096
#define DOUT   4096
#define RANK   256

#define STAGES    3
#define STG_BYTES (256 * 128)                   // (128 A rows + 128 B rows) x 128B
#define SMEM_SIZE (2048 + STAGES * STG_BYTES)   // 100352 B -> 2 CTAs/SM

// ---------------- scratch (static device globals: allocation-free) ----------------
__device__ __half g_xh[(size_t)TOKENS * DIN];   // x in fp16
__device__ __half g_wh[(size_t)DOUT * DIN];     // W = deq(Q) + deq(L) @ deq(R), fp16
__device__ __half g_lh[(size_t)DOUT * RANK];    // dequantized L  [out, rank]
__device__ __half g_rt[(size_t)DIN * RANK];     // dequantized R^T [in, rank]

// ---------------- small conversion kernels ----------------
__global__ void cvt_x_kernel(const float* __restrict__ x) {
    int i = blockIdx.x * blockDim.x + threadIdx.x;
    float4 v = reinterpret_cast<const float4*>(x)[i];
    __half2* o = reinterpret_cast<__half2*>(g_xh);
    o[2 * i]     = __floats2half2_rn(v.x, v.y);
    o[2 * i + 1] = __floats2half2_rn(v.z, v.w);
}

// groupwise dequant (row-major, cols = 2^cols_log2)
__global__ void deq_kernel(const int* __restrict__ v, const float* __restrict__ s,
                           __half* __restrict__ o, int cols_log2) {
    int i = blockIdx.x * blockDim.x + threadIdx.x;
    int4 q = reinterpret_cast<const int4*>(v)[i];
    int e = i << 2;
    int r = e >> cols_log2;
    int c = e & ((1 << cols_log2) - 1);
    float sc = s[(r << (cols_log2 - 7)) + (c >> 7)];
    __half2* po = reinterpret_cast<__half2*>(o);
    po[2 * i]     = __floats2half2_rn(q.x * sc, q.y * sc);
    po[2 * i + 1] = __floats2half2_rn(q.z * sc, q.w * sc);
}

// dequantize R [RANK, DIN] and write transposed R^T [DIN, RANK] via smem 64x64 tiles
__global__ void deq_rt_kernel(const int* __restrict__ rv, const float* __restrict__ rs) {
    __shared__ __half t[64][65];
    const int bi = blockIdx.x * 64;   // i (DIN) block
    const int br = blockIdx.y * 64;   // r (RANK) block
    const int tid = threadIdx.x;      // 256 threads
    #pragma unroll
    for (int j = 0; j < 16; j++) {
        int idx = tid + j * 256;
        int rl = idx >> 6;            // 0..63
        int il = idx & 63;
        int r = br + rl, i = bi + il;
        float sc = rs[r * (DIN / 128) + (i >> 7)];
        t[il][rl] = __float2half_rn(rv[(size_t)r * DIN + i] * sc);
    }
    __syncthreads();
    #pragma unroll
    for (int j = 0; j < 16; j++) {
        int idx = tid + j * 256;
        int il = idx >> 6;
        int rl = idx & 63;
        g_rt[(size_t)(bi + il) * RANK + br + rl] = t[il][rl];
    }
}

// ---------------- PTX helpers ----------------
__device__ __forceinline__ uint32_t smem_u32(const void* p) {
    uint32_t a;
    asm("{ .reg .u64 t; cvta.to.shared.u64 t, %1; cvt.u32.u64 %0, t; }" : "=r"(a) : "l"(p));
    return a;
}
#define MBARRIER_INIT(addr, cnt) \
    asm volatile("mbarrier.init.shared.b64 [%0], %1;" :: "r"(addr), "r"(cnt) : "memory")
#define MBARRIER_EXPECT_TX(addr, bytes) \
    asm volatile("mbarrier.arrive.expect_tx.shared.b64 _, [%0], %1;" \
                 :: "r"(addr), "r"(bytes) : "memory")
__device__ __forceinline__ void mbar_wait_parity(uint32_t mbar, uint32_t parity) {
    uint32_t done;
    asm volatile("{ .reg .pred p; mbarrier.try_wait.parity.acquire.cta.shared::cta.b64 p, [%1], %2;"
                 " selp.b32 %0, 1, 0, p; }" : "=r"(done) : "r"(mbar), "r"(parity) : "memory");
    if (!done) {
        asm volatile("{ .reg .pred P1; WL_%=:"
                     " mbarrier.try_wait.parity.acquire.cta.shared::cta.b64 P1, [%0], %1, 0x989680;"
                     " @P1 bra.uni WD_%=; bra.uni WL_%=; WD_%=: }"
                     :: "r"(mbar), "r"(parity) : "memory");
    }
}
#define TMA_LOAD_2D(dst, map, cx, cy, mbar) \
    asm volatile("cp.async.bulk.tensor.2d.shared::cta.global.tile.mbarrier::complete_tx::bytes " \
                 "[%0], [%1, {%2, %3}], [%4];" \
                 :: "r"(dst), "l"(map), "r"(cx), "r"(cy), "r"(mbar) : "memory")
#define FENCE_PROXY_ASYNC() asm volatile("fence.proxy.async.shared::cta;" ::: "memory")

__device__ __forceinline__ void ldsm4(uint32_t r[4], uint32_t addr) {
    asm volatile("ldmatrix.sync.aligned.m8n8.x4.shared.b16 {%0,%1,%2,%3}, [%4];\n"
                 : "=r"(r[0]), "=r"(r[1]), "=r"(r[2]), "=r"(r[3]) : "r"(addr));
}
__device__ __forceinline__ void mma16816(float c[4], const uint32_t a[4],
                                         uint32_t b0, uint32_t b1) {
    asm volatile("mma.sync.aligned.m16n8k16.row.col.f32.f16.f16.f32 "
                 "{%0,%1,%2,%3},{%4,%5,%6,%7},{%8,%9},{%0,%1,%2,%3};\n"
                 : "+f"(c[0]), "+f"(c[1]), "+f"(c[2]), "+f"(c[3])
                 : "r"(a[0]), "r"(a[1]), "r"(a[2]), "r"(a[3]), "r"(b0), "r"(b1));
}

// ------------------------------------------------------------------------------
// TMA-fed HMMA GEMM. CTA tile 128x128, BK=64, 8 warps as 2(M) x 4(N), warp 64x32.
// EPI==1: W-builder epilogue  -> outh[row,col] = acc + qv[row,col]*qs (fp16)
// EPI==2: main epilogue       -> outf[row,col] = acc + bias[col]      (fp32)
// ------------------------------------------------------------------------------
template <int TOTAL_ITERS, int EPI>
__global__ void __launch_bounds__(256, 2) tma_gemm_kernel(
    const __grid_constant__ CUtensorMap tmA,
    const __grid_constant__ CUtensorMap tmB,
    const int* __restrict__ qv, const float* __restrict__ qs,
    const float* __restrict__ bias,
    float* __restrict__ outf, __half* __restrict__ outh, int out_ld)
{
    extern __shared__ char smem[];
    const uint32_t sb    = smem_u32(smem);
    const uint32_t fullb = sb;                              // STAGES x 8B mbarriers
    const uint32_t tiles = (sb + 64 + 1023) & ~1023u;       // 1024-aligned for SW128

    const int tid  = threadIdx.x;
    const int lane = tid & 31;
    const int wid  = tid >> 5;
    const int wm   = wid >> 2;
    const int wn   = wid & 3;
    const int m0   = blockIdx.x * 128;
    const int n0   = blockIdx.y * 128;

    if (tid == 0) {
        #pragma unroll
        for (int s = 0; s < STAGES; s++) MBARRIER_INIT(fullb + 8 * s, 1);
        FENCE_PROXY_ASYNC();
    }
    __syncthreads();

    auto issue = [&](int kt, int st) {
        uint32_t da = tiles + st * STG_BYTES;
        uint32_t db = da + 128 * 128;
        MBARRIER_EXPECT_TX(fullb + 8 * st, STG_BYTES);
        TMA_LOAD_2D(da, &tmA, kt * 64, m0, fullb + 8 * st);
        TMA_LOAD_2D(db, &tmB, kt * 64, n0, fullb + 8 * st);
    };

    if (tid == 0) {
        #pragma unroll
        for (int p = 0; p < STAGES; p++)
            if (p < TOTAL_ITERS) issue(p, p);
    }

    float c[4][4][4];
    #pragma unroll
    for (int i = 0; i < 4; i++)
        #pragma unroll
        for (int j = 0; j < 4; j++)
            #pragma unroll
            for (int k = 0; k < 4; k++) c[i][j][k] = 0.f;

    const int lr = lane & 15;
    const int lc = lane >> 4;

    int st = 0, ph = 0;
    for (int kt = 0; kt < TOTAL_ITERS; kt++) {
        mbar_wait_parity(fullb + 8 * st, ph);

        const uint32_t sA = tiles + st * STG_BYTES;
        const uint32_t sB = sA + 128 * 128;

        #pragma unroll
        for (int ks = 0; ks < 4; ks++) {
            uint32_t a[4][4];
            uint32_t b[2][4];
            #pragma unroll
            for (int im = 0; im < 4; im++) {
                int row = wm * 64 + im * 16 + lr;
                int ch = (ks * 2 + lc) ^ (row & 7);
                ldsm4(a[im], sA + row * 128 + (ch << 4));
            }
            #pragma unroll
            for (int j = 0; j < 2; j++) {
                int row = wn * 32 + j * 16 + lr;
                int ch = (ks * 2 + lc) ^ (row & 7);
                ldsm4(b[j], sB + row * 128 + (ch << 4));
            }
            #pragma unroll
            for (int im = 0; im < 4; im++) {
                #pragma unroll
                for (int jn = 0; jn < 4; jn++) {
                    mma16816(c[im][jn], a[im], b[jn >> 1][jn & 1], b[jn >> 1][2 + (jn & 1)]);
                }
            }
        }

        __syncthreads();                       // all warps done reading stage st
        if (tid == 0 && kt + STAGES < TOTAL_ITERS) issue(kt + STAGES, st);

        if (++st == STAGES) { st = 0; ph ^= 1; }
    }

    // ---- epilogue ----
    #pragma unroll
    for (int im = 0; im < 4; im++) {
        #pragma unroll
        for (int jn = 0; jn < 4; jn++) {
            int row = m0 + wm * 64 + im * 16 + (lane >> 2);
            int col = n0 + wn * 32 + jn * 8 + (lane & 3) * 2;
            if constexpr (EPI == 1) {
                // W = LR_acc + deq(Q)
                #pragma unroll
                for (int h = 0; h < 2; h++) {
                    int r = row + 8 * h;
                    int2 q = *reinterpret_cast<const int2*>(&qv[(size_t)r * DIN + col]);
                    float sc = qs[r * (DIN / 128) + (col >> 7)];
                    __half2 v = __floats2half2_rn(c[im][jn][2 * h]     + q.x * sc,
                                                  c[im][jn][2 * h + 1] + q.y * sc);
                    *reinterpret_cast<__half2*>(&outh[(size_t)r * out_ld + col]) = v;
                }
            } else {
                float b0 = bias[col];
                float b1 = bias[col + 1];
                float2 v0 = make_float2(c[im][jn][0] + b0, c[im][jn][1] + b1);
                float2 v1 = make_float2(c[im][jn][2] + b0, c[im][jn][3] + b1);
                *reinterpret_cast<float2*>(outf + (size_t)row * out_ld + col) = v0;
                *reinterpret_cast<float2*>(outf + (size_t)(row + 8) * out_ld + col) = v1;
            }
        }
    }
}

// ---------------- host: tensor maps + launch ----------------
typedef CUresult (*EncodeTiledFn)(
    CUtensorMap*, CUtensorMapDataType, cuuint32_t, void*,
    const cuuint64_t*, const cuuint64_t*, const cuuint32_t*, const cuuint32_t*,
    CUtensorMapInterleave, CUtensorMapSwizzle, CUtensorMapL2promotion,
    CUtensorMapFloatOOBfill);

static void make_map_f16(EncodeTiledFn enc, CUtensorMap* tm, void* base,
                         uint64_t dim0, uint64_t dim1, uint64_t pitch_bytes) {
    uint64_t dims[2] = {dim0, dim1};
    uint64_t strides[1] = {pitch_bytes};
    uint32_t box[2] = {64, 128};
    uint32_t es[2] = {1, 1};
    enc(tm, CU_TENSOR_MAP_DATA_TYPE_FLOAT16, 2, base, dims, strides, box, es,
        CU_TENSOR_MAP_INTERLEAVE_NONE, CU_TENSOR_MAP_SWIZZLE_128B,
        CU_TENSOR_MAP_L2_PROMOTION_L2_128B, CU_TENSOR_MAP_FLOAT_OOB_FILL_NONE);
}

extern "C" void kernel_launch(void* const* d_in, const int* in_sizes, int n_in,
                              void* d_out, int out_size) {
    const float* x    = (const float*)d_in[0];
    const int*   qv   = (const int*)  d_in[1];
    const float* qs   = (const float*)d_in[2];
    const int*   lv   = (const int*)  d_in[3];
    const float* ls   = (const float*)d_in[4];
    const int*   rv   = (const int*)  d_in[5];
    const float* rs   = (const float*)d_in[6];
    const float* bias = (const float*)d_in[7];
    float* out = (float*)d_out;

    __half *pxh, *pwh, *plh, *prt;
    cudaGetSymbolAddress((void**)&pxh, g_xh);
    cudaGetSymbolAddress((void**)&pwh, g_wh);
    cudaGetSymbolAddress((void**)&plh, g_lh);
    cudaGetSymbolAddress((void**)&prt, g_rt);

    EncodeTiledFn enc = nullptr;
    {
        void* fp = nullptr;
        cudaDriverEntryPointQueryResult st;
        cudaGetDriverEntryPointByVersion("cuTensorMapEncodeTiled", &fp, 12000,
                                         cudaEnableDefault, &st);
        enc = (EncodeTiledFn)fp;
    }

    CUtensorMap tmX, tmW, tmL, tmRT;
    make_map_f16(enc, &tmX,  pxh, DIN,  TOKENS, (uint64_t)DIN * 2);
    make_map_f16(enc, &tmW,  pwh, DIN,  DOUT,   (uint64_t)DIN * 2);
    make_map_f16(enc, &tmL,  plh, RANK, DOUT,   (uint64_t)RANK * 2);
    make_map_f16(enc, &tmRT, prt, RANK, DIN,    (uint64_t)RANK * 2);

    auto kW    = tma_gemm_kernel<RANK / 64, 1>;   // W = L @ R^T(+Q), K=256
    auto kMain = tma_gemm_kernel<DIN / 64, 2>;    // out = x @ W^T + bias, K=4096
    cudaFuncSetAttribute(kW,    cudaFuncAttributeMaxDynamicSharedMemorySize, SMEM_SIZE);
    cudaFuncSetAttribute(kMain, cudaFuncAttributeMaxDynamicSharedMemorySize, SMEM_SIZE);

    // pre-pass
    cvt_x_kernel<<<(TOKENS * DIN / 4) / 256, 256>>>(x);
    deq_kernel<<<((size_t)DOUT * RANK / 4) / 256, 256>>>(lv, ls, plh, 8);   // L
    deq_rt_kernel<<<dim3(DIN / 64, RANK / 64), 256>>>(rv, rs);              // R^T

    // W = deq(L) @ deq(R)^T + deq(Q)   [DOUT, DIN] fp16
    kW<<<dim3(DOUT / 128, DIN / 128), 256, SMEM_SIZE>>>(
        tmL, tmRT, qv, qs, nullptr, nullptr, pwh, DIN);

    // out = x @ W^T + bias
    kMain<<<dim3(TOKENS / 128, DOUT / 128), 256, SMEM_SIZE>>>(
        tmX, tmW, nullptr, nullptr, bias, out, nullptr, DOUT);
}